// round 6
// baseline (speedup 1.0000x reference)
#include <cuda_runtime.h>
#include <cstdint>

#define B 8
#define T 4096
#define D 1024
#define S 64
#define SLOT_DIM 256
#define BOND 32
#define NQ 8
#define QDIM 256
#define NB 256          // blocks (2 per SM resident -> gbar safe)
#define NT 512          // threads per block
#define CPB 32          // chunks (blocks) per batch in streaming phases
#define RPB 128         // t-rows per block

// ------- device scratch (no allocations allowed) -------
__device__ float g_part[NB * D];         // partial column sums (1 MB)
__device__ float g_m0[B * 32];           // padded per batch
__device__ float g_m1[B * 32];
__device__ float g_overlaps[B * S];
__device__ float g_feats[S * NQ];
__device__ float g_fold[NQ * D];         // folded Wd (32 KB)
__device__ int   g_bar_count;            // zero-init
__device__ int   g_bar_gen;

// ---------------- software grid barrier (all NB blocks resident) ----------------
__device__ __forceinline__ void gbar() {
    __threadfence();
    __syncthreads();
    if (threadIdx.x == 0) {
        int gen = *(volatile int*)&g_bar_gen;
        if (atomicAdd(&g_bar_count, 1) == NB - 1) {
            *(volatile int*)&g_bar_count = 0;
            __threadfence();
            *(volatile int*)&g_bar_gen = gen + 1;
        } else {
            while (*(volatile int*)&g_bar_gen == gen) __nanosleep(64);
        }
    }
    __syncthreads();
}

__device__ __forceinline__ void l2_prefetch(const float* p) {
    asm volatile("prefetch.global.L2 [%0];" :: "l"(p));
}

__global__ void __launch_bounds__(NT, 2)
k_fused(const float* __restrict__ x,
        const float* __restrict__ Wq,
        const float* __restrict__ bq,
        const float* __restrict__ Wd,
        const float* __restrict__ bd,
        const float* __restrict__ cf,
        const float* __restrict__ cm,
        const float* __restrict__ cl,
        float* __restrict__ out) {
    __shared__ float smem[12288];   // 48 KB, aliased per phase
    const int blk = blockIdx.x;
    const int tid = threadIdx.x;
    const int b = blk >> 5;         // batch for streaming phases
    const int chunk = blk & 31;

    // ================= Phase 1: partial column sums (all blocks) =================
    {
        const int col4 = tid & 255;
        const int rq = tid >> 8;                 // 0/1 : row half
        const size_t row0 = (size_t)b * T + chunk * RPB + rq * 64;
        const float4* xp = reinterpret_cast<const float4*>(x) + row0 * 256 + col4;
        float4 acc = make_float4(0.f, 0.f, 0.f, 0.f);
#pragma unroll 8
        for (int r = 0; r < 64; ++r) {
            float4 v = xp[(size_t)r * 256];
            acc.x += v.x; acc.y += v.y; acc.z += v.z; acc.w += v.w;
        }
        reinterpret_cast<float4*>(smem)[rq * 256 + col4] = acc;
        __syncthreads();
        if (tid < 256) {
            float4 a = reinterpret_cast<float4*>(smem)[tid];
            float4 c4 = reinterpret_cast<float4*>(smem)[256 + tid];
            a.x += c4.x; a.y += c4.y; a.z += c4.z; a.w += c4.w;
            reinterpret_cast<float4*>(g_part)[blk * 256 + tid] = a;
        }
    }
    gbar();

    // ======== Phase 2 window: query (0..7) | fold Wd (8..39) | L2 prefetch (40..255) ========
    if (blk < B) {
        float* xs = smem;           // 1024
        float* pr = smem + 1024;    // 512 (2 x 256)
        float* qa = smem + 1536;    // 256
        float* red = smem + 1792;   // 8
        const int bb = blk;
        {
#pragma unroll
            for (int h = 0; h < 2; ++h) {
                const int d = tid + h * 512;
                float acc = 0.f;
#pragma unroll 8
                for (int p = 0; p < CPB; ++p)
                    acc += g_part[(bb * CPB + p) * D + d];
                xs[d] = acc * (1.0f / (float)T);
            }
        }
        __syncthreads();

        const int j = tid & 255;
        const int kc = tid >> 8;
        const int k0 = kc * 512;
        {
            float a = 0.f;
#pragma unroll 8
            for (int k = 0; k < 512; ++k)
                a = fmaf(xs[k0 + k], Wq[(size_t)(k0 + k) * QDIM + j], a);
            pr[kc * 256 + j] = a;
        }
        __syncthreads();

        float logit = 0.f;
        if (tid < QDIM) logit = pr[j] + pr[256 + j] + bq[j];

        float m = logit;
#pragma unroll
        for (int o = 16; o; o >>= 1) m = fmaxf(m, __shfl_xor_sync(0xffffffffu, m, o));
        if (tid < QDIM && (tid & 31) == 0) red[tid >> 5] = m;
        __syncthreads();
        float bm = red[0];
#pragma unroll
        for (int i = 1; i < 8; ++i) bm = fmaxf(bm, red[i]);
        float e = (tid < QDIM) ? __expf(logit - bm) : 0.f;
        float ssum = e;
#pragma unroll
        for (int o = 16; o; o >>= 1) ssum += __shfl_xor_sync(0xffffffffu, ssum, o);
        __syncthreads();
        if (tid < QDIM && (tid & 31) == 0) red[tid >> 5] = ssum;
        __syncthreads();
        float tot = 0.f;
#pragma unroll
        for (int i = 0; i < 8; ++i) tot += red[i];
        if (tid < QDIM) qa[j] = e / tot;
        __syncthreads();

        if (tid < 16) {   // amplitude means, JAX OOB-clamp to index 255
            const int q = tid & 7;
            const bool one = tid >= 8;
            const int s = 1 << (7 - q);
            const int cin = min(s, 128 / s);
            float a = 0.f;
            const int off = one ? s : 0;
            for (int i = 0; i < cin; ++i) a += qa[i * 2 * s + off];
            a += (float)(s - cin) * qa[QDIM - 1];
            float* dst = one ? g_m1 : g_m0;
            dst[bb * 32 + q] = a / (float)s;
        }
    } else if (blk < 40) {
        // fold[q][d] = sum_i Wd[i*8+q][d]  (independent of everything)
        if (tid < 256) {
            const int p = blk - 8;
            const int d = p * 32 + (tid >> 3);
            const int q = tid & 7;
            float acc = 0.f;
#pragma unroll 8
            for (int i = 0; i < 32; ++i)
                acc += Wd[(size_t)(i * 8 + q) * D + d];
            g_fold[q * D + d] = acc;
        }
    } else {
        // prefetch this block's phase-5 x region into L2 (fire and forget)
        const float* base = x + ((size_t)b * T + chunk * RPB) * D;
#pragma unroll
        for (int i = 0; i < 8; ++i)
            l2_prefetch(base + (size_t)(i * NT + tid) * 32);
    }
    gbar();

    // ================= Phase 3: slots (blocks 0..63 = slot) =================
    if (blk < S) {
        const int s = blk;
        {
            const float4* src = reinterpret_cast<const float4*>(cm + (size_t)s * 12288);
            float4* dst = reinterpret_cast<float4*>(smem);
#pragma unroll
            for (int i = 0; i < 6; ++i)
                dst[i * NT + tid] = src[i * NT + tid];
        }
        __syncthreads();

        if (tid < 256) {
            const int w = tid >> 5;
            const int lane = tid & 31;
            float fsum, inv_cnt;
            if (w == 0) {
                fsum = cf[s * 64 + lane] + cf[s * 64 + 32 + lane];
                inv_cnt = 1.0f / 64.0f;
            } else if (w == 7) {
                fsum = cl[s * 64 + lane] + cl[s * 64 + 32 + lane];
                inv_cnt = 1.0f / 64.0f;
            } else {
                const float* base = smem + (w - 1) * 2048;
                fsum = 0.f;
#pragma unroll
                for (int i = 0; i < 64; ++i) fsum += base[i * 32 + lane];
                inv_cnt = 1.0f / 2048.0f;
            }
#pragma unroll
            for (int o = 16; o; o >>= 1) fsum += __shfl_xor_sync(0xffffffffu, fsum, o);
            if (lane == 0) g_feats[s * NQ + w] = fsum * inv_cnt;

            const int bb = w;   // batch = warp
            float M0[NQ], M1[NQ];
#pragma unroll
            for (int q = 0; q < NQ; ++q) {
                M0[q] = __ldcg(&g_m0[bb * 32 + q]);
                M1[q] = __ldcg(&g_m1[bb * 32 + q]);
            }
            float v = M0[0] * cf[s * 64 + lane] + M1[0] * cf[s * 64 + 32 + lane];
#pragma unroll
            for (int q = 1; q <= NQ - 2; ++q) {
                const float* base = smem + (q - 1) * 2048;
                float nv = 0.f;
#pragma unroll 8
                for (int l = 0; l < BOND; ++l) {
                    float vl = __shfl_sync(0xffffffffu, v, l);
                    float c0 = base[l * 64 + lane];
                    float c1 = base[l * 64 + 32 + lane];
                    nv = fmaf(vl, fmaf(M0[q], c0, M1[q] * c1), nv);
                }
                v = nv;
            }
            float wl = M0[NQ - 1] * cl[(s * BOND + lane) * 2] +
                       M1[NQ - 1] * cl[(s * BOND + lane) * 2 + 1];
            float ov = v * wl;
#pragma unroll
            for (int o = 16; o; o >>= 1) ov += __shfl_xor_sync(0xffffffffu, ov, o);
            if (lane == 0) g_overlaps[bb * S + s] = ov;
        }
    }
    gbar();

    // ===== Phase 4+5 fused: per-block attention+gg, bias from fold, stream add =====
    {
        float* s_bias = smem;          // 1024
        float* s_gg = smem + 1024;     // 8

        if (tid < 32) {   // warp 0: attention + gg for this block's batch
            const int lane = tid;
            float a0 = __ldcg(&g_overlaps[b * S + lane]);
            float a1 = __ldcg(&g_overlaps[b * S + 32 + lane]);
            float m = fmaxf(a0, a1);
#pragma unroll
            for (int o = 16; o; o >>= 1) m = fmaxf(m, __shfl_xor_sync(0xffffffffu, m, o));
            float e0 = __expf(a0 - m);
            float e1 = __expf(a1 - m);
            float ssum = e0 + e1;
#pragma unroll
            for (int o = 16; o; o >>= 1) ssum += __shfl_xor_sync(0xffffffffu, ssum, o);
            const float inv = 1.0f / ssum;
            const float at0 = e0 * inv;
            const float at1 = e1 * inv;
#pragma unroll
            for (int q = 0; q < NQ; ++q) {
                float p = at0 * __ldcg(&g_feats[lane * NQ + q]) +
                          at1 * __ldcg(&g_feats[(32 + lane) * NQ + q]);
#pragma unroll
                for (int o = 16; o; o >>= 1) p += __shfl_xor_sync(0xffffffffu, p, o);
                if (lane == 0) s_gg[q] = p;
            }
        }
        __syncthreads();

        float gg[NQ];
#pragma unroll
        for (int q = 0; q < NQ; ++q) gg[q] = s_gg[q];
#pragma unroll
        for (int h = 0; h < 2; ++h) {
            const int d = tid + h * 512;
            float v = bd[d];
#pragma unroll
            for (int q = 0; q < NQ; ++q)
                v = fmaf(gg[q], __ldcg(&g_fold[q * D + d]), v);
            s_bias[d] = v;
        }
        __syncthreads();

        const int col4 = tid & 255;
        const int rq = tid >> 8;
        const size_t row0 = (size_t)b * T + chunk * RPB + rq * 64;
        const float4* xp = reinterpret_cast<const float4*>(x) + row0 * 256 + col4;
        float4* op = reinterpret_cast<float4*>(out) + row0 * 256 + col4;
        const float4 bias4 = reinterpret_cast<float4*>(s_bias)[col4];
#pragma unroll 8
        for (int r = 0; r < 64; ++r) {
            float4 v = xp[(size_t)r * 256];
            v.x += bias4.x; v.y += bias4.y; v.z += bias4.z; v.w += bias4.w;
            __stcs(&op[(size_t)r * 256], v);
        }
    }
}

extern "C" void kernel_launch(void* const* d_in, const int* in_sizes, int n_in,
                              void* d_out, int out_size) {
    const float* x  = (const float*)d_in[0];
    const float* Wq = (const float*)d_in[1];
    const float* bq = (const float*)d_in[2];
    const float* Wd = (const float*)d_in[3];
    const float* bd = (const float*)d_in[4];
    const float* cf = (const float*)d_in[5];
    const float* cm = (const float*)d_in[6];
    const float* cl = (const float*)d_in[7];
    float* out = (float*)d_out;

    k_fused<<<NB, NT>>>(x, Wq, bq, Wd, bd, cf, cm, cl, out);
}

// round 7
// speedup vs baseline: 1.3437x; 1.3437x over previous
#include <cuda_runtime.h>
#include <cstdint>

#define B 8
#define T 4096
#define D 1024
#define S 64
#define SLOT_DIM 256
#define BOND 32
#define NQ 8
#define QDIM 256
#define NB 128          // blocks (<= SM count -> all co-resident)
#define NT 1024         // threads per block
#define PB 16           // chunks (blocks) per batch
#define TB 256          // t-rows per block

// ------- device scratch (no allocations allowed) -------
__device__ float g_part[NB * D];         // partial column sums
__device__ float g_m0[B * 32];           // padded per batch
__device__ float g_m1[B * 32];
__device__ float g_overlaps[B * S];
__device__ float g_feats[S * NQ];
__device__ float g_fold[NQ * D];         // folded Wd (32 KB)
__device__ int   g_bar_count;            // zero-init
__device__ int   g_bar_gen;

// ---------------- software grid barrier (all NB blocks resident) ----------------
__device__ __forceinline__ void gbar() {
    __threadfence();
    __syncthreads();
    if (threadIdx.x == 0) {
        int gen = *(volatile int*)&g_bar_gen;
        if (atomicAdd(&g_bar_count, 1) == NB - 1) {
            *(volatile int*)&g_bar_count = 0;
            __threadfence();
            *(volatile int*)&g_bar_gen = gen + 1;
        } else {
            while (*(volatile int*)&g_bar_gen == gen) __nanosleep(64);
        }
    }
    __syncthreads();
}

__global__ void __launch_bounds__(NT, 1)
k_fused(const float* __restrict__ x,
        const float* __restrict__ Wq,
        const float* __restrict__ bq,
        const float* __restrict__ Wd,
        const float* __restrict__ bd,
        const float* __restrict__ cf,
        const float* __restrict__ cm,
        const float* __restrict__ cl,
        float* __restrict__ out) {
    __shared__ float smem[12288];   // 48 KB, aliased per phase
    const int blk = blockIdx.x;
    const int tid = threadIdx.x;

    // ================= Phase 1: partial column sums (all blocks) =================
    {
        const int b = blk >> 4;
        const int chunk = blk & 15;
        const int col4 = tid & 255;
        const int rq = tid >> 8;
        const size_t row0 = (size_t)b * T + chunk * TB + rq * 64;
        const float4* xp = reinterpret_cast<const float4*>(x) + row0 * 256 + col4;
        float4 acc = make_float4(0.f, 0.f, 0.f, 0.f);
#pragma unroll 8
        for (int r = 0; r < 64; ++r) {
            float4 v = xp[(size_t)r * 256];
            acc.x += v.x; acc.y += v.y; acc.z += v.z; acc.w += v.w;
        }
        reinterpret_cast<float4*>(smem)[rq * 256 + col4] = acc;
        __syncthreads();
        if (tid < 256) {
            float4 a = reinterpret_cast<float4*>(smem)[tid];
            float4 b4 = reinterpret_cast<float4*>(smem)[256 + tid];
            float4 c4 = reinterpret_cast<float4*>(smem)[512 + tid];
            float4 d4 = reinterpret_cast<float4*>(smem)[768 + tid];
            a.x = (a.x + b4.x) + (c4.x + d4.x);
            a.y = (a.y + b4.y) + (c4.y + d4.y);
            a.z = (a.z + b4.z) + (c4.z + d4.z);
            a.w = (a.w + b4.w) + (c4.w + d4.w);
            reinterpret_cast<float4*>(g_part)[blk * 256 + tid] = a;
        }
    }
    gbar();

    // ========= Phase 2 window: query (blocks 0..7) | fold Wd (blocks 8..39) =========
    if (blk < B) {
        float* xs = smem;           // 1024
        float* pr = smem + 1024;    // 1024 (4 x 256)
        float* qa = smem + 2048;    // 256
        float* red = smem + 2304;   // 8
        const int b = blk;
        {
            float acc = 0.f;
#pragma unroll
            for (int p = 0; p < PB; ++p)
                acc += g_part[(b * PB + p) * D + tid];
            xs[tid] = acc * (1.0f / (float)T);
        }
        __syncthreads();

        const int j = tid & 255;
        const int kc = tid >> 8;
        const int k0 = kc * 256;
        {
            float a = 0.f;
#pragma unroll 8
            for (int k = 0; k < 256; ++k)
                a = fmaf(xs[k0 + k], Wq[(size_t)(k0 + k) * QDIM + j], a);
            pr[kc * 256 + j] = a;
        }
        __syncthreads();

        float logit = 0.f;
        if (tid < QDIM)
            logit = (pr[j] + pr[256 + j]) + (pr[512 + j] + pr[768 + j]) + bq[j];

        // softmax over 256 — barriers in uniform control flow
        float m = logit;
#pragma unroll
        for (int o = 16; o; o >>= 1) m = fmaxf(m, __shfl_xor_sync(0xffffffffu, m, o));
        if (tid < QDIM && (tid & 31) == 0) red[tid >> 5] = m;
        __syncthreads();
        float bm = red[0];
#pragma unroll
        for (int i = 1; i < 8; ++i) bm = fmaxf(bm, red[i]);
        float e = (tid < QDIM) ? __expf(logit - bm) : 0.f;
        float ssum = e;
#pragma unroll
        for (int o = 16; o; o >>= 1) ssum += __shfl_xor_sync(0xffffffffu, ssum, o);
        __syncthreads();
        if (tid < QDIM && (tid & 31) == 0) red[tid >> 5] = ssum;
        __syncthreads();
        float tot = 0.f;
#pragma unroll
        for (int i = 0; i < 8; ++i) tot += red[i];
        if (tid < QDIM) qa[j] = e / tot;
        __syncthreads();

        if (tid < 16) {   // amplitude means, JAX OOB-clamp to index 255
            const int q = tid & 7;
            const bool one = tid >= 8;
            const int s = 1 << (7 - q);
            const int cin = min(s, 128 / s);
            float a = 0.f;
            const int off = one ? s : 0;
            for (int i = 0; i < cin; ++i) a += qa[i * 2 * s + off];
            a += (float)(s - cin) * qa[QDIM - 1];
            float* dst = one ? g_m1 : g_m0;
            dst[b * 32 + q] = a / (float)s;
        }
    } else if (blk < 40) {
        // fold[q][d] = sum_i Wd[i*8+q][d]   (x-independent)
        if (tid < 256) {
            const int p = blk - 8;
            const int d = p * 32 + (tid >> 3);
            const int q = tid & 7;
            float acc = 0.f;
#pragma unroll 8
            for (int i = 0; i < 32; ++i)
                acc += Wd[(size_t)(i * 8 + q) * D + d];
            g_fold[q * D + d] = acc;
        }
    }
    gbar();

    // ================= Phase 3: slots (blocks 0..63 = slot) =================
    if (blk < S) {
        const int s = blk;
        {
            const float4* src = reinterpret_cast<const float4*>(cm + (size_t)s * 12288);
            float4* dst = reinterpret_cast<float4*>(smem);
#pragma unroll
            for (int i = 0; i < 3; ++i)
                dst[i * 1024 + tid] = src[i * 1024 + tid];
        }
        __syncthreads();

        if (tid < 256) {
            const int w = tid >> 5;
            const int lane = tid & 31;
            float fsum, inv_cnt;
            if (w == 0) {
                fsum = cf[s * 64 + lane] + cf[s * 64 + 32 + lane];
                inv_cnt = 1.0f / 64.0f;
            } else if (w == 7) {
                fsum = cl[s * 64 + lane] + cl[s * 64 + 32 + lane];
                inv_cnt = 1.0f / 64.0f;
            } else {
                const float* base = smem + (w - 1) * 2048;
                fsum = 0.f;
#pragma unroll
                for (int i = 0; i < 64; ++i) fsum += base[i * 32 + lane];
                inv_cnt = 1.0f / 2048.0f;
            }
#pragma unroll
            for (int o = 16; o; o >>= 1) fsum += __shfl_xor_sync(0xffffffffu, fsum, o);
            if (lane == 0) g_feats[s * NQ + w] = fsum * inv_cnt;

            const int b = w;   // batch = warp
            float M0[NQ], M1[NQ];
#pragma unroll
            for (int q = 0; q < NQ; ++q) {
                M0[q] = __ldcg(&g_m0[b * 32 + q]);
                M1[q] = __ldcg(&g_m1[b * 32 + q]);
            }
            float v = M0[0] * cf[s * 64 + lane] + M1[0] * cf[s * 64 + 32 + lane];
#pragma unroll
            for (int q = 1; q <= NQ - 2; ++q) {
                const float* base = smem + (q - 1) * 2048;
                float nv = 0.f;
#pragma unroll 8
                for (int l = 0; l < BOND; ++l) {
                    float vl = __shfl_sync(0xffffffffu, v, l);
                    float c0 = base[l * 64 + lane];
                    float c1 = base[l * 64 + 32 + lane];
                    nv = fmaf(vl, fmaf(M0[q], c0, M1[q] * c1), nv);
                }
                v = nv;
            }
            float wl = M0[NQ - 1] * cl[(s * BOND + lane) * 2] +
                       M1[NQ - 1] * cl[(s * BOND + lane) * 2 + 1];
            float ov = v * wl;
#pragma unroll
            for (int o = 16; o; o >>= 1) ov += __shfl_xor_sync(0xffffffffu, ov, o);
            if (lane == 0) g_overlaps[b * S + s] = ov;
        }
    }
    gbar();

    // ===== Phase 4: per-block attention+gg, bias from fold, stream out = x + bias =====
    {
        const int kk = (NB - 1) - blk;   // reversed for L2 retention of x tail
        const int b = kk >> 4;
        const int chunk = kk & 15;

        float* s_bias = smem;          // 1024
        float* s_gg = smem + 1024;     // 8

        if (tid < 32) {   // warp 0: attention + gg for this block's batch
            const int lane = tid;
            float a0 = __ldcg(&g_overlaps[b * S + lane]);
            float a1 = __ldcg(&g_overlaps[b * S + 32 + lane]);
            float m = fmaxf(a0, a1);
#pragma unroll
            for (int o = 16; o; o >>= 1) m = fmaxf(m, __shfl_xor_sync(0xffffffffu, m, o));
            float e0 = __expf(a0 - m);
            float e1 = __expf(a1 - m);
            float ssum = e0 + e1;
#pragma unroll
            for (int o = 16; o; o >>= 1) ssum += __shfl_xor_sync(0xffffffffu, ssum, o);
            const float inv = 1.0f / ssum;
            const float at0 = e0 * inv;
            const float at1 = e1 * inv;
#pragma unroll
            for (int q = 0; q < NQ; ++q) {
                float p = at0 * __ldcg(&g_feats[lane * NQ + q]) +
                          at1 * __ldcg(&g_feats[(32 + lane) * NQ + q]);
#pragma unroll
                for (int o = 16; o; o >>= 1) p += __shfl_xor_sync(0xffffffffu, p, o);
                if (lane == 0) s_gg[q] = p;
            }
        }
        __syncthreads();

        {
            float gg[NQ];
#pragma unroll
            for (int q = 0; q < NQ; ++q) gg[q] = s_gg[q];
            float v = bd[tid];
#pragma unroll
            for (int q = 0; q < NQ; ++q)
                v = fmaf(gg[q], __ldcg(&g_fold[q * D + tid]), v);
            s_bias[tid] = v;
        }
        __syncthreads();

        const int col4 = tid & 255;
        const int rq = tid >> 8;
        const size_t row0 = (size_t)b * T + chunk * TB + rq * 64;
        const float4* xp = reinterpret_cast<const float4*>(x) + row0 * 256 + col4;
        float4* op = reinterpret_cast<float4*>(out) + row0 * 256 + col4;
        const float4 bias4 = reinterpret_cast<float4*>(s_bias)[col4];
#pragma unroll 8
        for (int r = 0; r < 64; ++r) {
            float4 v = xp[(size_t)r * 256];
            v.x += bias4.x; v.y += bias4.y; v.z += bias4.z; v.w += bias4.w;
            __stcs(&op[(size_t)r * 256], v);   // streaming store
        }
    }
}

extern "C" void kernel_launch(void* const* d_in, const int* in_sizes, int n_in,
                              void* d_out, int out_size) {
    const float* x  = (const float*)d_in[0];
    const float* Wq = (const float*)d_in[1];
    const float* bq = (const float*)d_in[2];
    const float* Wd = (const float*)d_in[3];
    const float* bd = (const float*)d_in[4];
    const float* cf = (const float*)d_in[5];
    const float* cm = (const float*)d_in[6];
    const float* cl = (const float*)d_in[7];
    float* out = (float*)d_out;

    k_fused<<<NB, NT>>>(x, Wq, bq, Wd, bd, cf, cm, cl, out);
}